// round 2
// baseline (speedup 1.0000x reference)
#include <cuda_runtime.h>
#include <cstdint>

#define N_ROUNDS 64
#define HID      256
#define NBATCH   8192
#define KW       64            // 256 k-elements / 4 per dp4a word
#define TILE_R   64            // batch rows per CTA
#define NTHREADS 512
#define NBLOCKS  (NBATCH / TILE_R)   // 128

// Pre-packed ternary matrices as int8x4 words: g_M[r][w][h] = M[r][h][4w..4w+3]
static __device__ uint32_t g_M[N_ROUNDS * KW * HID];   // 4 MB

__global__ void pack_matrices_kernel(const float* __restrict__ mats) {
    int idx = blockIdx.x * blockDim.x + threadIdx.x;   // exactly 64*256*64 threads
    int w = idx & (KW - 1);
    int h = (idx >> 6) & (HID - 1);
    int r = idx >> 14;
    const float4 v = *reinterpret_cast<const float4*>(
        mats + ((size_t)(r * HID + h) * HID + (w << 2)));
    uint32_t p = ((uint32_t)((int)v.x) & 0xFFu)
               | (((uint32_t)((int)v.y) & 0xFFu) << 8)
               | (((uint32_t)((int)v.z) & 0xFFu) << 16)
               | (((uint32_t)((int)v.w) & 0xFFu) << 24);
    g_M[(r * KW + w) * HID + h] = p;
}

__global__ __launch_bounds__(NTHREADS, 1) void tenshash_kernel(
    const int*   __restrict__ nonces,   // [8192, 32] int32, values 0..255
    const float* __restrict__ noise,    // [8192, 64, 256]; nonzero only at round 0
    float*       __restrict__ out)      // [8192, 256]
{
    extern __shared__ uint32_t smem[];
    uint32_t (*xs)[TILE_R] = reinterpret_cast<uint32_t(*)[TILE_R]>(smem);           // [KW][64]  16 KB
    uint32_t (*ms)[HID]    = reinterpret_cast<uint32_t(*)[HID]>(smem + KW * TILE_R); // [KW][256] 64 KB

    const int tid = threadIdx.x;
    const int b0  = blockIdx.x * TILE_R;

    // Init packed x from nonce bits: x[b][k] = (nonce_byte[k/8] >> (k%8)) & 1
    for (int i = tid; i < TILE_R * KW; i += NTHREADS) {
        int w   = i & (KW - 1);
        int row = i >> 6;
        int v   = nonces[(b0 + row) * 32 + (w >> 1)];
        int j0  = (w & 1) << 2;
        uint32_t p = ((uint32_t)((v >> j0) & 1))
                   | ((uint32_t)((v >> (j0 + 1)) & 1) << 8)
                   | ((uint32_t)((v >> (j0 + 2)) & 1) << 16)
                   | ((uint32_t)((v >> (j0 + 3)) & 1) << 24);
        xs[w][row] = p;
    }

    const int wg   = tid >> 5;       // warp id 0..15 -> 16 output cols each
    const int lane = tid & 31;       // lane -> 2 batch rows
    const int c0   = wg << 4;
    const int r0   = lane << 1;

    for (int r = 0; r < N_ROUNDS; r++) {
        // Stage this round's matrix (64 KB) into SMEM
        {
            const uint4* src = reinterpret_cast<const uint4*>(g_M + (size_t)r * (KW * HID));
            uint4* dst = reinterpret_cast<uint4*>(&ms[0][0]);
            #pragma unroll
            for (int i = 0; i < (KW * HID / 4) / NTHREADS; i++)   // 8 iters
                dst[tid + i * NTHREADS] = src[tid + i * NTHREADS];
        }
        __syncthreads();

        int acc[2][16];
        #pragma unroll
        for (int i = 0; i < 2; i++)
            #pragma unroll
            for (int j = 0; j < 16; j++) acc[i][j] = 0;

        #pragma unroll 8
        for (int w = 0; w < KW; w++) {
            // x: 2 rows, conflict-free LDS.64 (lane stride 8B)
            uint2 xv = *reinterpret_cast<const uint2*>(&xs[w][r0]);
            // M: 16 cols, uniform across the warp -> broadcast LDS.128 x4
            const uint4* mp = reinterpret_cast<const uint4*>(&ms[w][c0]);
            uint32_t mw[16];
            #pragma unroll
            for (int q = 0; q < 4; q++) {
                uint4 m = mp[q];
                mw[q * 4 + 0] = m.x; mw[q * 4 + 1] = m.y;
                mw[q * 4 + 2] = m.z; mw[q * 4 + 3] = m.w;
            }
            #pragma unroll
            for (int j = 0; j < 16; j++) {
                acc[0][j] = __dp4a((int)xv.x, (int)mw[j], acc[0][j]);
                acc[1][j] = __dp4a((int)xv.y, (int)mw[j], acc[1][j]);
            }
        }

        if (r == 0) {
            // noise is nonzero only at round 0 (sha256 gives 256 bits -> round 0 slice)
            #pragma unroll
            for (int i = 0; i < 2; i++)
                #pragma unroll
                for (int j = 0; j < 16; j++)
                    acc[i][j] += (int)noise[(size_t)(b0 + r0 + i) * (N_ROUNDS * HID) + (c0 + j)];
        }

        __syncthreads();   // all reads of xs complete before overwrite

        // x_new = s % 2 (C-style, matches fmod on integer-valued floats)
        #pragma unroll
        for (int jw = 0; jw < 4; jw++) {
            uint32_t lo = 0, hi = 0;
            #pragma unroll
            for (int t = 0; t < 4; t++) {
                lo |= ((uint32_t)(acc[0][jw * 4 + t] % 2) & 0xFFu) << (t * 8);
                hi |= ((uint32_t)(acc[1][jw * 4 + t] % 2) & 0xFFu) << (t * 8);
            }
            // STS.64: lane stride 8B, conflict-free
            *reinterpret_cast<uint2*>(&xs[(wg << 2) + jw][r0]) = make_uint2(lo, hi);
        }
        __syncthreads();
    }

    // Final: unpack int8 {-1,0,1} -> float32, coalesced over h
    for (int i = tid; i < TILE_R * HID; i += NTHREADS) {
        int row = i >> 8;
        int h   = i & (HID - 1);
        int8_t b = (int8_t)(xs[h >> 2][row] >> ((h & 3) << 3));
        out[(size_t)(b0 + row) * HID + h] = (float)b;
    }
}

extern "C" void kernel_launch(void* const* d_in, const int* in_sizes, int n_in,
                              void* d_out, int out_size) {
    const int*   nonces = (const int*)d_in[0];
    const float* mats   = (const float*)d_in[1];
    const float* noise  = (const float*)d_in[2];
    float*       out    = (float*)d_out;

    const int smem_bytes = (KW * TILE_R + KW * HID) * 4;   // 80 KB
    cudaFuncSetAttribute(tenshash_kernel,
                         cudaFuncAttributeMaxDynamicSharedMemorySize, smem_bytes);

    pack_matrices_kernel<<<(N_ROUNDS * HID * KW) / 256, 256>>>(mats);
    tenshash_kernel<<<NBLOCKS, NTHREADS, smem_bytes>>>(nonces, noise, out);
}

// round 4
// speedup vs baseline: 1.0026x; 1.0026x over previous
#include <cuda_runtime.h>
#include <cstdint>

#define N_ROUNDS 64
#define HID      256
#define NBATCH   8192
#define KW       64            // 256 k / 4 per int8x4 word
#define TILE_R   64            // batch rows per CTA
#define NTHREADS 512
#define NBLOCKS  (NBATCH / TILE_R)   // 128

#define XS_STRIDE 72           // padded word stride for x  (bank = (8w+row)%32)
#define MS_STRIDE 264          // padded word stride for M  (bank = (8w+n)%32)

// Pre-packed ternary matrices: g_M[r][w][h] = M[r][h][4w..4w+3] as int8x4
static __device__ uint32_t g_M[N_ROUNDS * KW * HID];   // 4 MB

__global__ void pack_matrices_kernel(const float* __restrict__ mats) {
    int idx = blockIdx.x * blockDim.x + threadIdx.x;   // 64*256*64 threads
    int w = idx & (KW - 1);
    int h = (idx >> 6) & (HID - 1);
    int r = idx >> 14;
    const float4 v = *reinterpret_cast<const float4*>(
        mats + ((size_t)(r * HID + h) * HID + (w << 2)));
    uint32_t p = ((uint32_t)((int)v.x) & 0xFFu)
               | (((uint32_t)((int)v.y) & 0xFFu) << 8)
               | (((uint32_t)((int)v.z) & 0xFFu) << 16)
               | (((uint32_t)((int)v.w) & 0xFFu) << 24);
    g_M[(r * KW + w) * HID + h] = p;
}

__device__ __forceinline__ uint32_t smem_u32(const void* p) {
    uint32_t a;
    asm("{ .reg .u64 t; cvta.to.shared.u64 t, %1; cvt.u32.u64 %0, t; }" : "=r"(a) : "l"(p));
    return a;
}
__device__ __forceinline__ void cp16(uint32_t dst, const void* src) {
    asm volatile("cp.async.cg.shared.global [%0], [%1], 16;" :: "r"(dst), "l"(src) : "memory");
}
__device__ __forceinline__ void imma(int* c, const uint32_t* a, const uint32_t* b) {
    asm volatile(
        "mma.sync.aligned.m16n8k32.row.col.s32.s8.s8.s32 "
        "{%0,%1,%2,%3}, {%4,%5,%6,%7}, {%8,%9}, {%0,%1,%2,%3};"
        : "+r"(c[0]), "+r"(c[1]), "+r"(c[2]), "+r"(c[3])
        : "r"(a[0]), "r"(a[1]), "r"(a[2]), "r"(a[3]), "r"(b[0]), "r"(b[1]));
}

__global__ __launch_bounds__(NTHREADS, 1) void tenshash_kernel(
    const int*   __restrict__ nonces,   // [8192, 32]
    const float* __restrict__ noise,    // [8192, 64, 256]; nonzero only round 0
    float*       __restrict__ out)      // [8192, 256]
{
    extern __shared__ uint32_t smem[];
    uint32_t* xs  = smem;                                  // [KW][72]   18.0 KB
    uint32_t* msb[2];
    msb[0] = smem + KW * XS_STRIDE;                        // [KW][264]  67.6 KB
    msb[1] = msb[0] + KW * MS_STRIDE;                      // [KW][264]  67.6 KB

    const int tid  = threadIdx.x;
    const int lane = tid & 31;
    const int wid  = tid >> 5;
    const int g    = lane >> 2;         // group id (row-ish)
    const int tg   = lane & 3;          // thread-in-group
    const int r0   = (wid & 1) * 32;    // warp's batch-row base (within tile)
    const int n0b  = (wid >> 1) * 32;   // warp's output-col base
    const int b0   = blockIdx.x * TILE_R;

    // ---- init packed x0 from nonce bits ----
    for (int i = tid; i < TILE_R * KW; i += NTHREADS) {
        int w   = i & (KW - 1);
        int row = i >> 6;
        int v   = nonces[(b0 + row) * 32 + (w >> 1)];
        int j0  = (w & 1) << 2;
        uint32_t p = ((uint32_t)((v >> j0) & 1))
                   | ((uint32_t)((v >> (j0 + 1)) & 1) << 8)
                   | ((uint32_t)((v >> (j0 + 2)) & 1) << 16)
                   | ((uint32_t)((v >> (j0 + 3)) & 1) << 24);
        xs[w * XS_STRIDE + row] = p;
    }

    // ---- stage round 0 matrix (double-buffered cp.async) ----
    const uint32_t ms_addr[2] = { smem_u32(msb[0]), smem_u32(msb[1]) };
    {
        const uint4* src = reinterpret_cast<const uint4*>(g_M);
        #pragma unroll
        for (int i = 0; i < 8; i++) {
            int idx = tid + i * NTHREADS;            // 4096 uint4
            int w = idx >> 6, h4 = idx & 63;
            cp16(ms_addr[0] + (uint32_t)(w * 66 + h4) * 16u, src + idx);
        }
        asm volatile("cp.async.commit_group;" ::: "memory");
    }

    int c[2][4][4];
    #pragma unroll
    for (int mi = 0; mi < 2; mi++)
        #pragma unroll
        for (int ni = 0; ni < 4; ni++)
            #pragma unroll
            for (int t = 0; t < 4; t++) c[mi][ni][t] = 0;

    for (int r = 0; r < N_ROUNDS; r++) {
        const uint32_t* ms = msb[r & 1];

        // prefetch next round's matrix into the other buffer
        if (r + 1 < N_ROUNDS) {
            const uint4* src = reinterpret_cast<const uint4*>(g_M + (size_t)(r + 1) * (KW * HID));
            uint32_t dst = ms_addr[(r + 1) & 1];
            #pragma unroll
            for (int i = 0; i < 8; i++) {
                int idx = tid + i * NTHREADS;
                int w = idx >> 6, h4 = idx & 63;
                cp16(dst + (uint32_t)(w * 66 + h4) * 16u, src + idx);
            }
            asm volatile("cp.async.commit_group;" ::: "memory");
            asm volatile("cp.async.wait_group 1;" ::: "memory");
        } else {
            asm volatile("cp.async.wait_group 0;" ::: "memory");
        }
        __syncthreads();   // ms[r] ready; prev-round xs stores visible

        // ---- 32x32 warp tile: 8 K-chunks x (2 m-subtiles x 4 n-subtiles) IMMA ----
        #pragma unroll
        for (int kc = 0; kc < 8; kc++) {
            const int wb = kc * 8;
            uint32_t a[2][4], b[4][2];
            #pragma unroll
            for (int mi = 0; mi < 2; mi++) {
                const int rr = r0 + mi * 16 + g;
                a[mi][0] = xs[(wb + tg) * XS_STRIDE + rr];
                a[mi][1] = xs[(wb + tg) * XS_STRIDE + rr + 8];
                a[mi][2] = xs[(wb + 4 + tg) * XS_STRIDE + rr];
                a[mi][3] = xs[(wb + 4 + tg) * XS_STRIDE + rr + 8];
            }
            #pragma unroll
            for (int ni = 0; ni < 4; ni++) {
                const int n = n0b + ni * 8 + g;
                b[ni][0] = ms[(wb + tg) * MS_STRIDE + n];
                b[ni][1] = ms[(wb + 4 + tg) * MS_STRIDE + n];
            }
            #pragma unroll
            for (int mi = 0; mi < 2; mi++)
                #pragma unroll
                for (int ni = 0; ni < 4; ni++)
                    imma(c[mi][ni], a[mi], b[ni]);
        }

        __syncthreads();   // all xs reads done before overwrite

        // ---- epilogue: (+noise r0) mod 2, repack, store ----
        #pragma unroll
        for (int mi = 0; mi < 2; mi++) {
            #pragma unroll
            for (int ni = 0; ni < 4; ni++) {
                int* cc = c[mi][ni];
                const int rowA = r0 + mi * 16 + g;
                const int colA = n0b + ni * 8 + tg * 2;
                if (r == 0) {
                    const float* np = noise + (size_t)(b0 + rowA) * (N_ROUNDS * HID) + colA;
                    const float* np8 = noise + (size_t)(b0 + rowA + 8) * (N_ROUNDS * HID) + colA;
                    cc[0] += (int)np[0];  cc[1] += (int)np[1];
                    cc[2] += (int)np8[0]; cc[3] += (int)np8[1];
                }
                int v0 = cc[0] % 2, v1 = cc[1] % 2, v2 = cc[2] % 2, v3 = cc[3] % 2;
                cc[0] = cc[1] = cc[2] = cc[3] = 0;
                if (r + 1 < N_ROUNDS) {
                    uint32_t plo = ((uint32_t)v0 & 0xFFu) | (((uint32_t)v1 & 0xFFu) << 8);
                    uint32_t phi = ((uint32_t)v2 & 0xFFu) | (((uint32_t)v3 & 0xFFu) << 8);
                    uint32_t qlo = __shfl_xor_sync(0xFFFFFFFFu, plo, 1);
                    uint32_t qhi = __shfl_xor_sync(0xFFFFFFFFu, phi, 1);
                    if ((tg & 1) == 0) {
                        const int w = ((n0b + ni * 8) >> 2) + (tg >> 1);
                        xs[w * XS_STRIDE + rowA]     = (plo & 0xFFFFu) | (qlo << 16);
                        xs[w * XS_STRIDE + rowA + 8] = (phi & 0xFFFFu) | (qhi << 16);
                    }
                } else {
                    float* o  = out + (size_t)(b0 + rowA) * HID + colA;
                    float* o8 = out + (size_t)(b0 + rowA + 8) * HID + colA;
                    o[0]  = (float)v0;  o[1]  = (float)v1;
                    o8[0] = (float)v2;  o8[1] = (float)v3;
                }
            }
        }
        __syncthreads();
    }
}

extern "C" void kernel_launch(void* const* d_in, const int* in_sizes, int n_in,
                              void* d_out, int out_size) {
    const int*   nonces = (const int*)d_in[0];
    const float* mats   = (const float*)d_in[1];
    const float* noise  = (const float*)d_in[2];
    float*       out    = (float*)d_out;

    const int smem_bytes = (KW * XS_STRIDE + 2 * KW * MS_STRIDE) * 4;   // 153600
    cudaFuncSetAttribute(tenshash_kernel,
                         cudaFuncAttributeMaxDynamicSharedMemorySize, smem_bytes);

    pack_matrices_kernel<<<(N_ROUNDS * HID * KW) / 256, 256>>>(mats);
    tenshash_kernel<<<NBLOCKS, NTHREADS, smem_bytes>>>(nonces, noise, out);
}

// round 8
// speedup vs baseline: 1.3451x; 1.3416x over previous
#include <cuda_runtime.h>
#include <cstdint>

#define N_ROUNDS 64
#define HID      256
#define NBATCH   8192
#define KW       64            // 256 k / 4 per int8x4 word
#define TILE_R   64            // batch rows per CTA
#define NTHREADS 512
#define NBLOCKS  (NBATCH / TILE_R)   // 128

#define XS_STRIDE 72           // padded word stride for x
#define MS_STRIDE 264          // padded word stride for M

// column split: tensor warps do [0, C_T), dp4a warps do [C_T, 256)
#define C_T      160
#define NSUB     5             // C_T / (4 warps * 8 cols)
#define DCOLS    12            // (256 - C_T) / 8 dp4a warps

// Pre-packed ternary matrices: g_M[r][w][h] = M[r][h][4w..4w+3] as int8x4
static __device__ uint32_t g_M[N_ROUNDS * KW * HID];   // 4 MB

__global__ void pack_matrices_kernel(const float* __restrict__ mats) {
    int idx = blockIdx.x * blockDim.x + threadIdx.x;   // 64*256*64 threads
    int w = idx & (KW - 1);
    int h = (idx >> 6) & (HID - 1);
    int r = idx >> 14;
    const float4 v = *reinterpret_cast<const float4*>(
        mats + ((size_t)(r * HID + h) * HID + (w << 2)));
    uint32_t p = ((uint32_t)((int)v.x) & 0xFFu)
               | (((uint32_t)((int)v.y) & 0xFFu) << 8)
               | (((uint32_t)((int)v.z) & 0xFFu) << 16)
               | (((uint32_t)((int)v.w) & 0xFFu) << 24);
    g_M[(r * KW + w) * HID + h] = p;
}

__device__ __forceinline__ uint32_t smem_u32(const void* p) {
    uint32_t a;
    asm("{ .reg .u64 t; cvta.to.shared.u64 t, %1; cvt.u32.u64 %0, t; }" : "=r"(a) : "l"(p));
    return a;
}
__device__ __forceinline__ void cp16(uint32_t dst, const void* src) {
    asm volatile("cp.async.cg.shared.global [%0], [%1], 16;" :: "r"(dst), "l"(src) : "memory");
}
__device__ __forceinline__ void imma(int* c, const uint32_t* a, const uint32_t* b) {
    asm volatile(
        "mma.sync.aligned.m16n8k32.row.col.s32.s8.s8.s32 "
        "{%0,%1,%2,%3}, {%4,%5,%6,%7}, {%8,%9}, {%0,%1,%2,%3};"
        : "+r"(c[0]), "+r"(c[1]), "+r"(c[2]), "+r"(c[3])
        : "r"(a[0]), "r"(a[1]), "r"(a[2]), "r"(a[3]), "r"(b[0]), "r"(b[1]));
}

__global__ __launch_bounds__(NTHREADS, 1) void tenshash_kernel(
    const int*   __restrict__ nonces,   // [8192, 32]
    const float* __restrict__ noise,    // [8192, 64, 256]; nonzero only round 0
    float*       __restrict__ out)      // [8192, 256]
{
    extern __shared__ uint32_t smem[];
    uint32_t* xs = smem;                                   // [KW][72]   18.0 KB
    uint32_t* msb[2];
    msb[0] = smem + KW * XS_STRIDE;                        // [KW][264]  67.6 KB
    msb[1] = msb[0] + KW * MS_STRIDE;                      // [KW][264]  67.6 KB

    const int tid  = threadIdx.x;
    const int lane = tid & 31;
    const int wid  = tid >> 5;
    const int b0   = blockIdx.x * TILE_R;

    // ---- init packed x0 from nonce bits ----
    for (int i = tid; i < TILE_R * KW; i += NTHREADS) {
        int w   = i & (KW - 1);
        int row = i >> 6;
        int v   = nonces[(b0 + row) * 32 + (w >> 1)];
        int j0  = (w & 1) << 2;
        uint32_t p = ((uint32_t)((v >> j0) & 1))
                   | ((uint32_t)((v >> (j0 + 1)) & 1) << 8)
                   | ((uint32_t)((v >> (j0 + 2)) & 1) << 16)
                   | ((uint32_t)((v >> (j0 + 3)) & 1) << 24);
        xs[w * XS_STRIDE + row] = p;
    }

    // ---- stage round 0 matrix (double-buffered cp.async) ----
    const uint32_t ms_addr[2] = { smem_u32(msb[0]), smem_u32(msb[1]) };
    {
        const uint4* src = reinterpret_cast<const uint4*>(g_M);
        #pragma unroll
        for (int i = 0; i < 8; i++) {
            int idx = tid + i * NTHREADS;            // 4096 uint4
            int w = idx >> 6, h4 = idx & 63;
            cp16(ms_addr[0] + (uint32_t)(w * 66 + h4) * 16u, src + idx);
        }
        asm volatile("cp.async.commit_group;" ::: "memory");
    }

    const bool is_tensor = (wid < 8);
    // tensor-warp coords
    const int g  = lane >> 2;
    const int tg = lane & 3;
    const int r0t  = (wid & 1) * 32;          // batch-row base
    const int n0b  = (wid >> 1) * (NSUB * 8); // output-col base (0,40,80,120)
    // dp4a-warp coords
    const int dwid = wid - 8;
    const int c0d  = C_T + dwid * DCOLS;      // output-col base (160..244)
    const int r0d  = lane << 1;               // 2 batch rows per lane

    int c[2][NSUB][4];
    if (is_tensor) {
        #pragma unroll
        for (int mi = 0; mi < 2; mi++)
            #pragma unroll
            for (int ni = 0; ni < NSUB; ni++)
                #pragma unroll
                for (int t = 0; t < 4; t++) c[mi][ni][t] = 0;
    }

    for (int r = 0; r < N_ROUNDS; r++) {
        const uint32_t* ms = msb[r & 1];

        // prefetch next round's matrix into the other buffer
        if (r + 1 < N_ROUNDS) {
            const uint4* src = reinterpret_cast<const uint4*>(g_M + (size_t)(r + 1) * (KW * HID));
            uint32_t dst = ms_addr[(r + 1) & 1];
            #pragma unroll
            for (int i = 0; i < 8; i++) {
                int idx = tid + i * NTHREADS;
                int w = idx >> 6, h4 = idx & 63;
                cp16(dst + (uint32_t)(w * 66 + h4) * 16u, src + idx);
            }
            asm volatile("cp.async.commit_group;" ::: "memory");
            asm volatile("cp.async.wait_group 1;" ::: "memory");
        } else {
            asm volatile("cp.async.wait_group 0;" ::: "memory");
        }
        __syncthreads();   // ms[r] ready; prev-round xs stores visible

        if (is_tensor) {
            // ---- tensor path: 32 x 40 warp tile, cols [0, 160) ----
            #pragma unroll
            for (int kc = 0; kc < 8; kc++) {
                const int wb = kc * 8;
                uint32_t a[2][4], b[NSUB][2];
                #pragma unroll
                for (int mi = 0; mi < 2; mi++) {
                    const int rr = r0t + mi * 16 + g;
                    a[mi][0] = xs[(wb + tg) * XS_STRIDE + rr];
                    a[mi][1] = xs[(wb + tg) * XS_STRIDE + rr + 8];
                    a[mi][2] = xs[(wb + 4 + tg) * XS_STRIDE + rr];
                    a[mi][3] = xs[(wb + 4 + tg) * XS_STRIDE + rr + 8];
                }
                #pragma unroll
                for (int ni = 0; ni < NSUB; ni++) {
                    const int n = n0b + ni * 8 + g;
                    b[ni][0] = ms[(wb + tg) * MS_STRIDE + n];
                    b[ni][1] = ms[(wb + 4 + tg) * MS_STRIDE + n];
                }
                #pragma unroll
                for (int mi = 0; mi < 2; mi++)
                    #pragma unroll
                    for (int ni = 0; ni < NSUB; ni++)
                        imma(c[mi][ni], a[mi], b[ni]);
            }
        } else {
            // ---- dp4a path: 64 x 12 warp tile, cols [160, 256) ----
            int acc[2][DCOLS];
            #pragma unroll
            for (int i = 0; i < 2; i++)
                #pragma unroll
                for (int j = 0; j < DCOLS; j++) acc[i][j] = 0;

            #pragma unroll 8
            for (int w = 0; w < KW; w++) {
                uint2 xv = *reinterpret_cast<const uint2*>(&xs[w * XS_STRIDE + r0d]);
                const uint4* mp = reinterpret_cast<const uint4*>(&ms[w * MS_STRIDE + c0d]);
                uint32_t mw[DCOLS];
                #pragma unroll
                for (int q = 0; q < DCOLS / 4; q++) {
                    uint4 m = mp[q];
                    mw[q * 4 + 0] = m.x; mw[q * 4 + 1] = m.y;
                    mw[q * 4 + 2] = m.z; mw[q * 4 + 3] = m.w;
                }
                #pragma unroll
                for (int j = 0; j < DCOLS; j++) {
                    acc[0][j] = __dp4a((int)xv.x, (int)mw[j], acc[0][j]);
                    acc[1][j] = __dp4a((int)xv.y, (int)mw[j], acc[1][j]);
                }
            }

            if (r == 0) {
                #pragma unroll
                for (int i = 0; i < 2; i++) {
                    const float* np = noise + (size_t)(b0 + r0d + i) * (N_ROUNDS * HID) + c0d;
                    #pragma unroll
                    for (int j = 0; j < DCOLS; j++) acc[i][j] += (int)np[j];
                }
            }

            __syncthreads();   // pair with tensor warps' post-compute barrier

            if (r + 1 < N_ROUNDS) {
                #pragma unroll
                for (int jw = 0; jw < DCOLS / 4; jw++) {
                    uint32_t lo = 0, hi = 0;
                    #pragma unroll
                    for (int t = 0; t < 4; t++) {
                        lo |= ((uint32_t)(acc[0][jw * 4 + t] % 2) & 0xFFu) << (t * 8);
                        hi |= ((uint32_t)(acc[1][jw * 4 + t] % 2) & 0xFFu) << (t * 8);
                    }
                    const int w = (c0d >> 2) + jw;
                    *reinterpret_cast<uint2*>(&xs[w * XS_STRIDE + r0d]) = make_uint2(lo, hi);
                }
            } else {
                #pragma unroll
                for (int i = 0; i < 2; i++) {
                    float* o = out + (size_t)(b0 + r0d + i) * HID + c0d;
                    #pragma unroll
                    for (int j = 0; j < DCOLS; j++) o[j] = (float)(acc[i][j] % 2);
                }
            }
            __syncthreads();
            continue;
        }

        __syncthreads();   // all xs reads done before overwrite

        // ---- tensor epilogue: (+noise r0) mod 2, repack, store ----
        #pragma unroll
        for (int mi = 0; mi < 2; mi++) {
            #pragma unroll
            for (int ni = 0; ni < NSUB; ni++) {
                int* cc = c[mi][ni];
                const int rowA = r0t + mi * 16 + g;
                const int colA = n0b + ni * 8 + tg * 2;
                if (r == 0) {
                    const float* np  = noise + (size_t)(b0 + rowA) * (N_ROUNDS * HID) + colA;
                    const float* np8 = noise + (size_t)(b0 + rowA + 8) * (N_ROUNDS * HID) + colA;
                    cc[0] += (int)np[0];  cc[1] += (int)np[1];
                    cc[2] += (int)np8[0]; cc[3] += (int)np8[1];
                }
                int v0 = cc[0] % 2, v1 = cc[1] % 2, v2 = cc[2] % 2, v3 = cc[3] % 2;
                cc[0] = cc[1] = cc[2] = cc[3] = 0;
                if (r + 1 < N_ROUNDS) {
                    uint32_t plo = ((uint32_t)v0 & 0xFFu) | (((uint32_t)v1 & 0xFFu) << 8);
                    uint32_t phi = ((uint32_t)v2 & 0xFFu) | (((uint32_t)v3 & 0xFFu) << 8);
                    uint32_t qlo = __shfl_xor_sync(0xFFFFFFFFu, plo, 1);
                    uint32_t qhi = __shfl_xor_sync(0xFFFFFFFFu, phi, 1);
                    if ((tg & 1) == 0) {
                        const int w = ((n0b + ni * 8) >> 2) + (tg >> 1);
                        xs[w * XS_STRIDE + rowA]     = (plo & 0xFFFFu) | (qlo << 16);
                        xs[w * XS_STRIDE + rowA + 8] = (phi & 0xFFFFu) | (qhi << 16);
                    }
                } else {
                    float* o  = out + (size_t)(b0 + rowA) * HID + colA;
                    float* o8 = out + (size_t)(b0 + rowA + 8) * HID + colA;
                    o[0]  = (float)v0;  o[1]  = (float)v1;
                    o8[0] = (float)v2;  o8[1] = (float)v3;
                }
            }
        }
        __syncthreads();
    }
}

extern "C" void kernel_launch(void* const* d_in, const int* in_sizes, int n_in,
                              void* d_out, int out_size) {
    const int*   nonces = (const int*)d_in[0];
    const float* mats   = (const float*)d_in[1];
    const float* noise  = (const float*)d_in[2];
    float*       out    = (float*)d_out;

    const int smem_bytes = (KW * XS_STRIDE + 2 * KW * MS_STRIDE) * 4;   // 153600
    cudaFuncSetAttribute(tenshash_kernel,
                         cudaFuncAttributeMaxDynamicSharedMemorySize, smem_bytes);

    pack_matrices_kernel<<<(N_ROUNDS * HID * KW) / 256, 256>>>(mats);
    tenshash_kernel<<<NBLOCKS, NTHREADS, smem_bytes>>>(nonces, noise, out);
}